// round 17
// baseline (speedup 1.0000x reference)
#include <cuda_runtime.h>
#include <math.h>

#define H 1024
#define W 1024
#define HW (H*W)
#define TX 56
#define TY 32
#define GR 40     // gray/hblur rows (TY + 8)
#define BW 60     // hblur/blurred width (TX + 4)
#define BR 36     // blurred rows (TY + 4)
#define MW 58     // msq width (TX + 2)
#define MH 34     // msq rows (TY + 2)
#define NT 512
#define NBX 19    // ceil(1024/56)
#define MPLANE (MH*MW)   // 1972 floats per msq plane

typedef unsigned long long u64;

__device__ int g_count = 0;
__device__ int g_ticket = 0;

__device__ __forceinline__ u64 pk(float lo, float hi) {
    u64 r; asm("mov.b64 %0,{%1,%2};" : "=l"(r) : "f"(lo), "f"(hi)); return r;
}
__device__ __forceinline__ void upk(u64 v, float& lo, float& hi) {
    asm("mov.b64 {%0,%1},%2;" : "=f"(lo), "=f"(hi) : "l"(v));
}
__device__ __forceinline__ u64 fadd2(u64 a, u64 b) {
    u64 r; asm("add.rn.f32x2 %0,%1,%2;" : "=l"(r) : "l"(a), "l"(b)); return r;
}
__device__ __forceinline__ u64 fmul2(u64 a, u64 b) {
    u64 r; asm("mul.rn.f32x2 %0,%1,%2;" : "=l"(r) : "l"(a), "l"(b)); return r;
}
__device__ __forceinline__ u64 ffma2(u64 a, u64 b, u64 c) {
    u64 r; asm("fma.rn.f32x2 %0,%1,%2,%3;" : "=l"(r) : "l"(a), "l"(b), "l"(c)); return r;
}
__device__ __forceinline__ u64 fneg2(u64 a) { return a ^ 0x8000000080000000ULL; }
__device__ __forceinline__ u64 fsub2(u64 a, u64 b) { return fadd2(a, fneg2(b)); }

__device__ __forceinline__ int reflecti(int c, int n) {
    if (c < 0) c = -c;
    if (c >= n) c = 2*n - 2 - c;
    return c;
}

#define GW0 0.05448868454964294f
#define GW1 0.24420134723186663f
#define GW2 0.4026199364369709f
#define T_LO 0.41421356237309503f
#define T_HI 2.414213562373095f
#define TH2  0.009999f

__device__ __forceinline__ int axis_off(float gx, float gy) {
    float ax = fabsf(gx), ay = fabsf(gy);
    if (ay <= T_LO * ax) return 1;
    if (ay >= T_HI * ax) return MW;
    return ((__float_as_int(gx) ^ __float_as_int(gy)) >= 0) ? (MW - 1) : (MW + 1);
}

__device__ __forceinline__ u64 tap5(u64 t0, u64 t1, u64 t2, u64 t3, u64 t4,
                                    u64 K0, u64 K1, u64 K2) {
    u64 acc = fmul2(fadd2(t0, t4), K0);
    acc = ffma2(fadd2(t1, t3), K1, acc);
    return ffma2(t2, K2, acc);
}

__global__ __launch_bounds__(NT, 4)
void edge_loss_kernel(const float* __restrict__ op, const float* __restrict__ gt,
                      float* __restrict__ out, float inv_n)
{
    __shared__ u64   bufA[GR * BW];   // hblur -> later 2 planar msq fields
    __shared__ u64   bufB[BR * BW];   // blurred
    __shared__ short snoff[TY * TX];
    __shared__ int   wsum[NT / 32];

    float* msqO = (float*)bufA;            // [MH*MW] op-plane
    float* msqG = msqO + MPLANE;           // [MH*MW] gt-plane

    const int tid  = threadIdx.x;
    const int lane = tid & 31;
    const int wid  = tid >> 5;
    const int x0 = blockIdx.x * TX;
    const int y0 = blockIdx.y * TY;
    const size_t ib = (size_t)blockIdx.z * 3 * HW;
    const float* __restrict__ opi = op + ib;
    const float* __restrict__ gti = gt + ib;

    const u64 K0 = pk(GW0, GW0), K1 = pk(GW1, GW1), K2 = pk(GW2, GW2);
    const u64 TWO = pk(2.0f, 2.0f);

    const bool xedge = (blockIdx.x == 0) || (blockIdx.x == NBX - 1);
    const int  c0  = x0 - 4 + 2 * lane;
    const int  rc0 = reflecti(c0, W), rc1 = reflecti(c0 + 1, W);

    // ---- Stage 1+2 fused: gray (reflect) + hblur via shfl -> bufA[GR][BW] ----
    #pragma unroll 1
    for (int r = wid; r < GR; r += NT / 32) {
        int yy = reflecti(y0 - 4 + r, H);
        const float* ro = opi + yy * W;
        const float* rg = gti + yy * W;
        float ao0, ao1, ag0, ag1;
        if (!xedge) {
            float2 r_o = *(const float2*)(ro + c0);
            float2 g_o = *(const float2*)(ro + HW + c0);
            float2 b_o = *(const float2*)(ro + 2*HW + c0);
            float2 r_g = *(const float2*)(rg + c0);
            float2 g_g = *(const float2*)(rg + HW + c0);
            float2 b_g = *(const float2*)(rg + 2*HW + c0);
            ao0 = fmaf(0.299f, r_o.x, fmaf(0.587f, g_o.x, 0.114f*b_o.x));
            ao1 = fmaf(0.299f, r_o.y, fmaf(0.587f, g_o.y, 0.114f*b_o.y));
            ag0 = fmaf(0.299f, r_g.x, fmaf(0.587f, g_g.x, 0.114f*b_g.x));
            ag1 = fmaf(0.299f, r_g.y, fmaf(0.587f, g_g.y, 0.114f*b_g.y));
        } else {
            ao0 = fmaf(0.299f, ro[rc0], fmaf(0.587f, ro[HW+rc0], 0.114f*ro[2*HW+rc0]));
            ao1 = fmaf(0.299f, ro[rc1], fmaf(0.587f, ro[HW+rc1], 0.114f*ro[2*HW+rc1]));
            ag0 = fmaf(0.299f, rg[rc0], fmaf(0.587f, rg[HW+rc0], 0.114f*rg[2*HW+rc0]));
            ag1 = fmaf(0.299f, rg[rc1], fmaf(0.587f, rg[HW+rc1], 0.114f*rg[2*HW+rc1]));
        }
        u64 g0 = pk(ao0, ag0), g1 = pk(ao1, ag1);
        u64 gm0 = __shfl_up_sync(0xffffffffu, g0, 1);
        u64 gm1 = __shfl_up_sync(0xffffffffu, g1, 1);
        u64 gp0 = __shfl_down_sync(0xffffffffu, g0, 1);
        u64 gp1 = __shfl_down_sync(0xffffffffu, g1, 1);
        u64 h0 = tap5(gm0, gm1, g0, g1, gp0, K0, K1, K2);
        u64 h1 = tap5(gm1, g0, g1, gp0, gp1, K0, K1, K2);
        if (lane >= 1 && lane <= 30)
            *(ulonglong2*)&bufA[r * BW + 2*lane - 2] = make_ulonglong2(h0, h1);
    }
    __syncthreads();

    // ---- Stage 3: vblur 3-tall x 1-wide -> bufB[BR][BW] ----
    #pragma unroll 1
    for (int s = tid; s < (BR/3) * BW; s += NT) {
        int rg = s / BW;
        int j = s - rg * BW;
        int r0 = rg * 3;
        const u64* col = &bufA[r0 * BW + j];
        u64 t0 = col[0],    t1 = col[BW],   t2 = col[2*BW], t3 = col[3*BW];
        u64 t4 = col[4*BW], t5 = col[5*BW], t6 = col[6*BW];
        bufB[(r0 + 0) * BW + j] = tap5(t0, t1, t2, t3, t4, K0, K1, K2);
        bufB[(r0 + 1) * BW + j] = tap5(t1, t2, t3, t4, t5, K0, K1, K2);
        bufB[(r0 + 2) * BW + j] = tap5(t2, t3, t4, t5, t6, K0, K1, K2);
    }
    __syncthreads();

    // ---- Patches: x edge-clamp then y edge-clamp of blurred field ----
    if (blockIdx.x == 0) {
        #pragma unroll 1
        for (int r = tid; r < BR; r += NT) {
            u64 v = bufB[r * BW + 2];
            bufB[r * BW + 0] = v;
            bufB[r * BW + 1] = v;
        }
        __syncthreads();
    } else if (blockIdx.x == NBX - 1) {
        int blast = (W - 1) - (x0 - 2);
        #pragma unroll 1
        for (int r = tid; r < BR; r += NT) {
            u64 v = bufB[r * BW + blast];
            bufB[r * BW + blast + 1] = v;
            bufB[r * BW + blast + 2] = v;
        }
        __syncthreads();
    }
    if (y0 == 0) {
        #pragma unroll 1
        for (int j = tid; j < BW; j += NT) {
            u64 v = bufB[2 * BW + j];
            bufB[0 * BW + j] = v;
            bufB[1 * BW + j] = v;
        }
        __syncthreads();
    } else if (y0 == H - TY) {
        #pragma unroll 1
        for (int j = tid; j < BW; j += NT) {
            u64 v = bufB[33 * BW + j];
            bufB[34 * BW + j] = v;
            bufB[35 * BW + j] = v;
        }
        __syncthreads();
    }

    // ---- Stage 4: separable Sobel, column-per-lane + shfl, 2 msq rows/task ----
    // Lane owns blurred col c; s = b0+2b1+b2 (colsum), d = b2-b0 (coldiff).
    // gx(m) = s(m+2)-s(m), gy(m) = d(m)+2d(m+1)+d(m+2); lane at c=m+1 outputs m.
    // Tasks: 17 row-pairs x 2 col-segments (c0 = 0 / 28). Overlap cols store
    // identical values (benign).
    #pragma unroll 1
    for (int ip = wid; ip < 34; ip += NT / 32) {
        int rp = ip >> 1;
        int i0 = rp << 1;                   // msq rows i0, i0+1
        int cseg = (ip & 1) ? 28 : 0;
        int c = cseg + lane;                // blurred col 0..59
        const u64* colp = &bufB[i0 * BW + c];
        u64 b0 = colp[0], b1 = colp[BW], b2 = colp[2*BW], b3 = colp[3*BW];

        int m = c - 1;
        bool lvalid = (lane >= 1) && (lane <= 30);
        int x = x0 - 1 + m;
        bool xok = (unsigned)x < W;

        #pragma unroll
        for (int r = 0; r < 2; r++) {
            u64 ta = r ? b1 : b0;
            u64 tb = r ? b2 : b1;
            u64 tc = r ? b3 : b2;
            u64 s = ffma2(tb, TWO, fadd2(ta, tc));
            u64 d = fsub2(tc, ta);
            u64 sL = __shfl_up_sync(0xffffffffu, s, 1);
            u64 sR = __shfl_down_sync(0xffffffffu, s, 1);
            u64 dL = __shfl_up_sync(0xffffffffu, d, 1);
            u64 dR = __shfl_down_sync(0xffffffffu, d, 1);
            u64 gx = fsub2(sR, sL);
            u64 gy = ffma2(d, TWO, fadd2(dL, dR));
            int i = i0 + r;
            int y = y0 - 1 + i;
            u64 msq = ffma2(gx, gx, fmul2(gy, gy));
            if (!((unsigned)y < H && xok)) msq = 0ULL;
            if (lvalid) {
                float mo, mg;
                upk(msq, mo, mg);
                int mi = i * MW + m;
                msqO[mi] = mo;
                msqG[mi] = mg;
                if (i >= 1 && i <= TY && m >= 1 && m <= TX) {
                    float gxo, gxg, gyo, gyg;
                    upk(gx, gxo, gxg); upk(gy, gyo, gyg);
                    int oo = axis_off(gxo, gyo);
                    int og = axis_off(gxg, gyg);
                    snoff[(i - 1) * TX + (m - 1)] = (short)(oo | (og << 8));
                }
            }
        }
    }
    __syncthreads();

    // ---- Stage 5: NMS + threshold + XOR count (planar, stride-4B loads) ----
    int cnt = 0;
    #pragma unroll
    for (int k = 0; k < 4; k++) {
        int px = tid + k * NT;
        if (px < TY * TX) {
            int i = px / TX, j = px - i * TX;
            int ci = (i + 1) * MW + (j + 1);
            float co = msqO[ci];
            float cg = msqG[ci];
            int sv = snoff[px];
            int oo = sv & 0xff;
            int og = (sv >> 8) & 0xff;
            bool eo = (co > msqO[ci + oo]) & (co > msqO[ci - oo]) & (co > TH2);
            bool eg = (cg > msqG[ci + og]) & (cg > msqG[ci - og]) & (cg > TH2);
            cnt += (int)(eo != eg);
        }
    }

    // ---- block reduce + fused finalize ----
    #pragma unroll
    for (int o = 16; o > 0; o >>= 1)
        cnt += __shfl_down_sync(0xffffffffu, cnt, o);
    if ((tid & 31) == 0) wsum[tid >> 5] = cnt;
    __syncthreads();
    if (tid < (NT / 32)) {
        cnt = wsum[tid];
        #pragma unroll
        for (int o = (NT / 64); o > 0; o >>= 1)
            cnt += __shfl_down_sync(0xffffu, cnt, o);
        if (tid == 0) {
            atomicAdd(&g_count, cnt);
            __threadfence();
            int nb = gridDim.x * gridDim.y * gridDim.z;
            int t = atomicAdd(&g_ticket, 1);
            if (t == nb - 1) {
                out[0] = (float)atomicAdd(&g_count, 0) * inv_n;
                g_count = 0;
                g_ticket = 0;
            }
        }
    }
}

extern "C" void kernel_launch(void* const* d_in, const int* in_sizes, int n_in,
                              void* d_out, int out_size)
{
    const float* op = (const float*)d_in[0];
    const float* gt = (const float*)d_in[1];
    float* out = (float*)d_out;

    int batch = in_sizes[0] / (3 * HW);
    float inv_n = 1.0f / ((float)batch * HW);

    dim3 grid(NBX, H / TY, batch);
    edge_loss_kernel<<<grid, NT>>>(op, gt, out, inv_n);
}